// round 1
// baseline (speedup 1.0000x reference)
#include <cuda_runtime.h>

#define BB    4
#define NN    8192
#define ALPHA 5.0f
#define EPS   1e-12f

#define QB    64      // queries (threads) per knn block
#define TILE  1024    // ref points per smem tile (16 KB of float4)

__device__ float4 g_ref4[BB * NN];
__device__ float  g_dsum[BB * NN];
__device__ float  g_bsum[BB];

// Pack (x, y, z, ||p||^2) for coalesced float4 loads later.
__global__ void k_prep(const float* __restrict__ xyz) {
    int i = blockIdx.x * blockDim.x + threadIdx.x;
    if (i < BB * NN) {
        float x = xyz[3 * i + 0];
        float y = xyz[3 * i + 1];
        float z = xyz[3 * i + 2];
        float sq = (x * x + y * y) + z * z;   // match jnp.sum order
        g_ref4[i] = make_float4(x, y, z, sq);
    }
}

// One thread per query point; refs streamed through shared memory tiles.
// Tracks the two smallest d2 (self-distance ~0 included), branchless.
__global__ void __launch_bounds__(QB) k_knn() {
    __shared__ float4 s_ref[TILE];

    const int b  = blockIdx.y;
    const int qi = blockIdx.x * QB + threadIdx.x;

    const float4 q = g_ref4[b * NN + qi];
    const float mx = -2.0f * q.x;
    const float my = -2.0f * q.y;
    const float mz = -2.0f * q.z;
    const float sqi = q.w;

    float d0 = 3.4e38f;   // smallest d2
    float d1 = 3.4e38f;   // second smallest d2

    const float4* __restrict__ refb = &g_ref4[b * NN];

    for (int t = 0; t < NN; t += TILE) {
        __syncthreads();
        #pragma unroll
        for (int j = threadIdx.x; j < TILE; j += QB)
            s_ref[j] = refb[t + j];
        __syncthreads();

        #pragma unroll 4
        for (int j = 0; j < TILE; j++) {
            float4 r = s_ref[j];
            // d2 = sq_i + sq_j - 2*dot  (expanded form, matches reference numerics)
            float d2 = fmaf(mx, r.x, fmaf(my, r.y, fmaf(mz, r.z, sqi + r.w)));
            float hi = fmaxf(d2, d0);
            d0 = fminf(d2, d0);
            d1 = fminf(hi, d1);
        }
    }

    float dsum = sqrtf(fmaxf(d0, EPS)) + sqrtf(fmaxf(d1, EPS));
    g_dsum[b * NN + qi] = dsum;
}

__device__ __forceinline__ float block_reduce_sum(float v) {
    __shared__ float sh[32];
    int lane = threadIdx.x & 31;
    int wid  = threadIdx.x >> 5;
    #pragma unroll
    for (int o = 16; o; o >>= 1) v += __shfl_down_sync(0xFFFFFFFFu, v, o);
    if (lane == 0) sh[wid] = v;
    __syncthreads();
    int nw = (blockDim.x + 31) >> 5;
    v = (threadIdx.x < nw) ? sh[threadIdx.x] : 0.0f;
    if (wid == 0) {
        #pragma unroll
        for (int o = 16; o; o >>= 1) v += __shfl_down_sync(0xFFFFFFFFu, v, o);
    }
    return v;   // valid in thread 0
}

// grid = BB blocks: per-batch sum of dsum
__global__ void k_bsum() {
    int b = blockIdx.x;
    float s = 0.0f;
    for (int i = threadIdx.x; i < NN; i += blockDim.x)
        s += g_dsum[b * NN + i];
    s = block_reduce_sum(s);
    if (threadIdx.x == 0) g_bsum[b] = s;
}

__global__ void k_zero(float* out) { out[0] = 0.0f; }

// grid = BB blocks: masked sum of dsum where dsum > (bsum/N)*ALPHA
__global__ void k_loss(float* __restrict__ out) {
    int b = blockIdx.x;
    float avg = g_bsum[b] / (float)NN;   // mean first, then *ALPHA (matches ref op order)
    float thr = avg * ALPHA;
    float s = 0.0f;
    for (int i = threadIdx.x; i < NN; i += blockDim.x) {
        float d = g_dsum[b * NN + i];
        if (d > thr) s += d;
    }
    s = block_reduce_sum(s);
    if (threadIdx.x == 0) atomicAdd(out, s);
}

extern "C" void kernel_launch(void* const* d_in, const int* in_sizes, int n_in,
                              void* d_out, int out_size) {
    const float* xyz = (const float*)d_in[0];
    float* out = (float*)d_out;

    k_prep<<<(BB * NN + 255) / 256, 256>>>(xyz);

    dim3 grid(NN / QB, BB);
    k_knn<<<grid, QB>>>();

    k_zero<<<1, 1>>>(out);
    k_bsum<<<BB, 256>>>();
    k_loss<<<BB, 256>>>(out);
}

// round 2
// speedup vs baseline: 1.1243x; 1.1243x over previous
#include <cuda_runtime.h>

#define BB    4
#define NN    8192
#define ALPHA 5.0f
#define EPS   1e-12f

#define QB    64       // threads per knn block
#define QPT   2        // queries per thread
#define TILEP 512      // ref PAIRS per smem tile (1024 refs, 16 KB)

typedef unsigned long long ull;

// Packed ref pairs: pkA[p] = {x0,x1,y0,y1}, pkB[p] = {z0,z1,w0,w1}
__device__ float4 g_pkA[BB * NN / 2];
__device__ float4 g_pkB[BB * NN / 2];
__device__ float4 g_q4 [BB * NN];      // per-point (x,y,z,||p||^2) for query loads
__device__ float  g_dsum[BB * NN];
__device__ float  g_bsum[BB];

__device__ __forceinline__ ull f2u(float a, float b) {
    union { float f[2]; ull u; } t; t.f[0] = a; t.f[1] = b; return t.u;
}
__device__ __forceinline__ void u2f(ull v, float& a, float& b) {
    union { float f[2]; ull u; } t; t.u = v; a = t.f[0]; b = t.f[1];
}
__device__ __forceinline__ ull add2(ull a, ull b) {
    ull d; asm("add.rn.f32x2 %0, %1, %2;" : "=l"(d) : "l"(a), "l"(b)); return d;
}
__device__ __forceinline__ ull fma2(ull a, ull b, ull c) {
    ull d; asm("fma.rn.f32x2 %0, %1, %2, %3;" : "=l"(d) : "l"(a), "l"(b), "l"(c)); return d;
}

// Pack (x, y, z, ||p||^2); also zero accumulators (runs before k_knn/k_loss).
__global__ void k_prep(const float* __restrict__ xyz, float* __restrict__ out) {
    int p = blockIdx.x * blockDim.x + threadIdx.x;     // pair index
    if (p < BB * NN / 2) {
        int i0 = 2 * p, i1 = 2 * p + 1;
        float x0 = xyz[3*i0+0], y0 = xyz[3*i0+1], z0 = xyz[3*i0+2];
        float x1 = xyz[3*i1+0], y1 = xyz[3*i1+1], z1 = xyz[3*i1+2];
        float w0 = (x0*x0 + y0*y0) + z0*z0;            // match jnp.sum order
        float w1 = (x1*x1 + y1*y1) + z1*z1;
        g_pkA[p] = make_float4(x0, x1, y0, y1);
        g_pkB[p] = make_float4(z0, z1, w0, w1);
        g_q4[i0] = make_float4(x0, y0, z0, w0);
        g_q4[i1] = make_float4(x1, y1, z1, w1);
    }
    if (p == 0) {
        out[0] = 0.0f;
        #pragma unroll
        for (int b = 0; b < BB; b++) g_bsum[b] = 0.0f;
    }
}

// Per-query running two smallest d2, refs tiled through smem as packed pairs.
// Window of 4 refs: packed fma for d2, FMNMX tree for 2-smallest, then merge.
__global__ void __launch_bounds__(QB) k_knn() {
    __shared__ float4 sA[TILEP];
    __shared__ float4 sB[TILEP];

    const int b   = blockIdx.y;
    const int tid = threadIdx.x;
    const int q0  = blockIdx.x * (QB * QPT) + tid;     // query A
    const int q1  = q0 + QB;                           // query B

    float4 qa = g_q4[b * NN + q0];
    float4 qb = g_q4[b * NN + q1];
    const ull mxA = f2u(-2.0f*qa.x, -2.0f*qa.x), myA = f2u(-2.0f*qa.y, -2.0f*qa.y);
    const ull mzA = f2u(-2.0f*qa.z, -2.0f*qa.z), sqA = f2u(qa.w, qa.w);
    const ull mxB = f2u(-2.0f*qb.x, -2.0f*qb.x), myB = f2u(-2.0f*qb.y, -2.0f*qb.y);
    const ull mzB = f2u(-2.0f*qb.z, -2.0f*qb.z), sqB = f2u(qb.w, qb.w);

    float a0 = 3.4e38f, a1 = 3.4e38f;   // two smallest d2 for query A
    float b0 = 3.4e38f, b1 = 3.4e38f;   // two smallest d2 for query B

    const float4* __restrict__ pA = &g_pkA[b * (NN/2)];
    const float4* __restrict__ pB = &g_pkB[b * (NN/2)];

    for (int t = 0; t < NN/2; t += TILEP) {
        __syncthreads();
        #pragma unroll
        for (int j = tid; j < TILEP; j += QB) {
            sA[j] = pA[t + j];
            sB[j] = pB[t + j];
        }
        __syncthreads();

        #pragma unroll 2
        for (int j = 0; j < TILEP; j += 2) {
            float4 A0 = sA[j],   B0 = sB[j];      // refs 2j, 2j+1
            float4 A1 = sA[j+1], B1 = sB[j+1];    // refs 2j+2, 2j+3
            ull x0 = f2u(A0.x, A0.y), y0 = f2u(A0.z, A0.w);
            ull z0 = f2u(B0.x, B0.y), w0 = f2u(B0.z, B0.w);
            ull x1 = f2u(A1.x, A1.y), y1 = f2u(A1.z, A1.w);
            ull z1 = f2u(B1.x, B1.y), w1 = f2u(B1.z, B1.w);

            // ---- query A: 4 d2 values via packed fma ----
            ull ta0 = fma2(mxA, x0, fma2(myA, y0, fma2(mzA, z0, add2(sqA, w0))));
            ull ta1 = fma2(mxA, x1, fma2(myA, y1, fma2(mzA, z1, add2(sqA, w1))));
            {
                float c0, c1, c2, c3;
                u2f(ta0, c0, c1); u2f(ta1, c2, c3);
                float m1 = fminf(c0, c1), M1 = fmaxf(c0, c1);
                float m2 = fminf(c2, c3), M2 = fmaxf(c2, c3);
                float v0 = fminf(m1, m2);
                float v1 = fminf(fmaxf(m1, m2), fminf(M1, M2));
                float n0 = fminf(v0, a0);
                float tt = fmaxf(v0, a0);
                float uu = fminf(v1, a1);
                a0 = n0; a1 = fminf(tt, uu);
            }
            // ---- query B ----
            ull tb0 = fma2(mxB, x0, fma2(myB, y0, fma2(mzB, z0, add2(sqB, w0))));
            ull tb1 = fma2(mxB, x1, fma2(myB, y1, fma2(mzB, z1, add2(sqB, w1))));
            {
                float c0, c1, c2, c3;
                u2f(tb0, c0, c1); u2f(tb1, c2, c3);
                float m1 = fminf(c0, c1), M1 = fmaxf(c0, c1);
                float m2 = fminf(c2, c3), M2 = fmaxf(c2, c3);
                float v0 = fminf(m1, m2);
                float v1 = fminf(fmaxf(m1, m2), fminf(M1, M2));
                float n0 = fminf(v0, b0);
                float tt = fmaxf(v0, b0);
                float uu = fminf(v1, b1);
                b0 = n0; b1 = fminf(tt, uu);
            }
        }
    }

    float dsA = sqrtf(fmaxf(a0, EPS)) + sqrtf(fmaxf(a1, EPS));
    float dsB = sqrtf(fmaxf(b0, EPS)) + sqrtf(fmaxf(b1, EPS));
    g_dsum[b * NN + q0] = dsA;
    g_dsum[b * NN + q1] = dsB;

    // fused per-batch sum: block reduce then one atomic
    float s = dsA + dsB;
    #pragma unroll
    for (int o = 16; o; o >>= 1) s += __shfl_down_sync(0xFFFFFFFFu, s, o);
    __shared__ float sh[QB / 32];
    if ((tid & 31) == 0) sh[tid >> 5] = s;
    __syncthreads();
    if (tid == 0) {
        float tot = sh[0];
        #pragma unroll
        for (int w = 1; w < QB / 32; w++) tot += sh[w];
        atomicAdd(&g_bsum[b], tot);
    }
}

__device__ __forceinline__ float block_reduce_sum(float v) {
    __shared__ float sh[32];
    int lane = threadIdx.x & 31;
    int wid  = threadIdx.x >> 5;
    #pragma unroll
    for (int o = 16; o; o >>= 1) v += __shfl_down_sync(0xFFFFFFFFu, v, o);
    if (lane == 0) sh[wid] = v;
    __syncthreads();
    int nw = (blockDim.x + 31) >> 5;
    v = (threadIdx.x < nw) ? sh[threadIdx.x] : 0.0f;
    if (wid == 0) {
        #pragma unroll
        for (int o = 16; o; o >>= 1) v += __shfl_down_sync(0xFFFFFFFFu, v, o);
    }
    return v;
}

// grid = BB: masked sum of dsum where dsum > (bsum/N)*ALPHA
__global__ void k_loss(float* __restrict__ out) {
    int b = blockIdx.x;
    float avg = g_bsum[b] / (float)NN;   // mean first, then *ALPHA (ref op order)
    float thr = avg * ALPHA;
    float s = 0.0f;
    for (int i = threadIdx.x; i < NN; i += blockDim.x) {
        float d = g_dsum[b * NN + i];
        if (d > thr) s += d;
    }
    s = block_reduce_sum(s);
    if (threadIdx.x == 0) atomicAdd(out, s);
}

extern "C" void kernel_launch(void* const* d_in, const int* in_sizes, int n_in,
                              void* d_out, int out_size) {
    const float* xyz = (const float*)d_in[0];
    float* out = (float*)d_out;

    k_prep<<<(BB * NN / 2 + 255) / 256, 256>>>(xyz, out);

    dim3 grid(NN / (QB * QPT), BB);
    k_knn<<<grid, QB>>>();

    k_loss<<<BB, 256>>>(out);
}

// round 3
// speedup vs baseline: 1.3822x; 1.2294x over previous
#include <cuda_runtime.h>

#define BB    4
#define NN    8192
#define ALPHA 5.0f
#define EPS   1e-12f

#define SPLIT 4                 // ref-dimension split for occupancy
#define SLICE (NN / SPLIT)      // 2048 refs per block
#define SLICEP (SLICE / 2)      // 1024 ref pairs per block
#define QB    128               // threads per knn block
#define QPT   2                 // queries per thread

typedef unsigned long long ull;

// Packed ref pairs: pkA[p] = {x0,x1,y0,y1}, pkB[p] = {z0,z1,w0,w1}
__device__ float4 g_pkA[BB * NN / 2];
__device__ float4 g_pkB[BB * NN / 2];
__device__ float4 g_q4 [BB * NN];           // per-point (x,y,z,||p||^2)
__device__ float2 g_part[BB * SPLIT * NN];  // per-(batch,slice,query) sorted 2-min
__device__ float  g_dsum[BB * NN];
__device__ float  g_bsum[BB];

__device__ __forceinline__ ull f2u(float a, float b) {
    union { float f[2]; ull u; } t; t.f[0] = a; t.f[1] = b; return t.u;
}
__device__ __forceinline__ void u2f(ull v, float& a, float& b) {
    union { float f[2]; ull u; } t; t.u = v; a = t.f[0]; b = t.f[1];
}
__device__ __forceinline__ ull add2(ull a, ull b) {
    ull d; asm("add.rn.f32x2 %0, %1, %2;" : "=l"(d) : "l"(a), "l"(b)); return d;
}
__device__ __forceinline__ ull fma2(ull a, ull b, ull c) {
    ull d; asm("fma.rn.f32x2 %0, %1, %2, %3;" : "=l"(d) : "l"(a), "l"(b), "l"(c)); return d;
}

// Pack (x, y, z, ||p||^2); zero accumulators. Aligned float2 loads (6p floats).
__global__ void k_prep(const float* __restrict__ xyz, float* __restrict__ out) {
    int p = blockIdx.x * blockDim.x + threadIdx.x;     // pair index
    if (p < BB * NN / 2) {
        const float2* g = (const float2*)xyz;
        float2 f0 = g[3*p+0], f1 = g[3*p+1], f2 = g[3*p+2];
        float x0 = f0.x, y0 = f0.y, z0 = f1.x;
        float x1 = f1.y, y1 = f2.x, z1 = f2.y;
        float w0 = (x0*x0 + y0*y0) + z0*z0;            // match jnp.sum order
        float w1 = (x1*x1 + y1*y1) + z1*z1;
        g_pkA[p] = make_float4(x0, x1, y0, y1);
        g_pkB[p] = make_float4(z0, z1, w0, w1);
        g_q4[2*p]   = make_float4(x0, y0, z0, w0);
        g_q4[2*p+1] = make_float4(x1, y1, z1, w1);
    }
    if (p == 0) {
        out[0] = 0.0f;
        #pragma unroll
        for (int b = 0; b < BB; b++) g_bsum[b] = 0.0f;
    }
}

// Each block: 256 queries vs a 2048-ref slice (held entirely in smem).
// Emits per-query partial sorted two smallest d2.
__global__ void __launch_bounds__(QB) k_knn() {
    __shared__ float4 sA[SLICEP];
    __shared__ float4 sB[SLICEP];

    const int b     = blockIdx.y;
    const int slice = blockIdx.z;
    const int tid   = threadIdx.x;
    const int q0    = blockIdx.x * (QB * QPT) + tid;   // query A
    const int q1    = q0 + QB;                         // query B

    const float4* __restrict__ pA = &g_pkA[b * (NN/2) + slice * SLICEP];
    const float4* __restrict__ pB = &g_pkB[b * (NN/2) + slice * SLICEP];
    #pragma unroll
    for (int j = tid; j < SLICEP; j += QB) {
        sA[j] = pA[j];
        sB[j] = pB[j];
    }

    float4 qa = g_q4[b * NN + q0];
    float4 qb = g_q4[b * NN + q1];
    const ull mxA = f2u(-2.0f*qa.x, -2.0f*qa.x), myA = f2u(-2.0f*qa.y, -2.0f*qa.y);
    const ull mzA = f2u(-2.0f*qa.z, -2.0f*qa.z), sqA = f2u(qa.w, qa.w);
    const ull mxB = f2u(-2.0f*qb.x, -2.0f*qb.x), myB = f2u(-2.0f*qb.y, -2.0f*qb.y);
    const ull mzB = f2u(-2.0f*qb.z, -2.0f*qb.z), sqB = f2u(qb.w, qb.w);

    float a0 = 3.4e38f, a1 = 3.4e38f;   // two smallest d2, query A (a0<=a1)
    float b0 = 3.4e38f, b1 = 3.4e38f;   // two smallest d2, query B

    __syncthreads();

    #pragma unroll 2
    for (int j = 0; j < SLICEP; j += 2) {
        float4 A0 = sA[j],   B0 = sB[j];
        float4 A1 = sA[j+1], B1 = sB[j+1];
        ull x0 = f2u(A0.x, A0.y), y0 = f2u(A0.z, A0.w);
        ull z0 = f2u(B0.x, B0.y), w0 = f2u(B0.z, B0.w);
        ull x1 = f2u(A1.x, A1.y), y1 = f2u(A1.z, A1.w);
        ull z1 = f2u(B1.x, B1.y), w1 = f2u(B1.z, B1.w);

        // ---- query A ----
        ull ta0 = fma2(mxA, x0, fma2(myA, y0, fma2(mzA, z0, add2(sqA, w0))));
        ull ta1 = fma2(mxA, x1, fma2(myA, y1, fma2(mzA, z1, add2(sqA, w1))));
        {
            float c0, c1, c2, c3;
            u2f(ta0, c0, c1); u2f(ta1, c2, c3);
            float m1 = fminf(c0, c1), M1 = fmaxf(c0, c1);
            float m2 = fminf(c2, c3), M2 = fmaxf(c2, c3);
            float v0 = fminf(m1, m2);
            float v1 = fminf(fmaxf(m1, m2), fminf(M1, M2));
            float n0 = fminf(v0, a0);
            float tt = fmaxf(v0, a0);
            float uu = fminf(v1, a1);
            a0 = n0; a1 = fminf(tt, uu);
        }
        // ---- query B ----
        ull tb0 = fma2(mxB, x0, fma2(myB, y0, fma2(mzB, z0, add2(sqB, w0))));
        ull tb1 = fma2(mxB, x1, fma2(myB, y1, fma2(mzB, z1, add2(sqB, w1))));
        {
            float c0, c1, c2, c3;
            u2f(tb0, c0, c1); u2f(tb1, c2, c3);
            float m1 = fminf(c0, c1), M1 = fmaxf(c0, c1);
            float m2 = fminf(c2, c3), M2 = fmaxf(c2, c3);
            float v0 = fminf(m1, m2);
            float v1 = fminf(fmaxf(m1, m2), fminf(M1, M2));
            float n0 = fminf(v0, b0);
            float tt = fmaxf(v0, b0);
            float uu = fminf(v1, b1);
            b0 = n0; b1 = fminf(tt, uu);
        }
    }

    float2* dst = &g_part[(b * SPLIT + slice) * NN];
    dst[q0] = make_float2(a0, a1);
    dst[q1] = make_float2(b0, b1);
}

__device__ __forceinline__ float block_reduce_sum(float v) {
    __shared__ float sh[32];
    int lane = threadIdx.x & 31;
    int wid  = threadIdx.x >> 5;
    #pragma unroll
    for (int o = 16; o; o >>= 1) v += __shfl_down_sync(0xFFFFFFFFu, v, o);
    if (lane == 0) sh[wid] = v;
    __syncthreads();
    int nw = (blockDim.x + 31) >> 5;
    v = (threadIdx.x < nw) ? sh[threadIdx.x] : 0.0f;
    if (wid == 0) {
        #pragma unroll
        for (int o = 16; o; o >>= 1) v += __shfl_down_sync(0xFFFFFFFFu, v, o);
    }
    return v;
}

// Merge two sorted pairs -> smallest two of the union (exact).
__device__ __forceinline__ float2 merge2(float2 a, float2 b) {
    float v0 = fminf(a.x, b.x);
    float v1 = fminf(fmaxf(a.x, b.x), fminf(a.y, b.y));
    return make_float2(v0, v1);
}

// One thread per query: merge SPLIT partials, compute dsum, batch-sum.
__global__ void k_merge() {
    int i = blockIdx.x * blockDim.x + threadIdx.x;     // global query idx
    int b = i / NN;
    int q = i - b * NN;
    float2 m = g_part[(b * SPLIT + 0) * NN + q];
    #pragma unroll
    for (int s = 1; s < SPLIT; s++)
        m = merge2(m, g_part[(b * SPLIT + s) * NN + q]);
    float ds = sqrtf(fmaxf(m.x, EPS)) + sqrtf(fmaxf(m.y, EPS));
    g_dsum[i] = ds;
    float t = block_reduce_sum(ds);                    // block spans one batch
    if (threadIdx.x == 0) atomicAdd(&g_bsum[b], t);
}

// grid = BB: masked sum where dsum > (bsum/N)*ALPHA
__global__ void k_loss(float* __restrict__ out) {
    int b = blockIdx.x;
    float avg = g_bsum[b] / (float)NN;   // mean first, then *ALPHA (ref op order)
    float thr = avg * ALPHA;
    float s = 0.0f;
    for (int i = threadIdx.x; i < NN; i += blockDim.x) {
        float d = g_dsum[b * NN + i];
        if (d > thr) s += d;
    }
    s = block_reduce_sum(s);
    if (threadIdx.x == 0) atomicAdd(out, s);
}

extern "C" void kernel_launch(void* const* d_in, const int* in_sizes, int n_in,
                              void* d_out, int out_size) {
    const float* xyz = (const float*)d_in[0];
    float* out = (float*)d_out;

    k_prep<<<(BB * NN / 2 + 255) / 256, 256>>>(xyz, out);

    dim3 grid(NN / (QB * QPT), BB, SPLIT);   // 32 x 4 x 4 = 512 blocks, 2048 warps
    k_knn<<<grid, QB>>>();

    k_merge<<<BB * NN / 256, 256>>>();       // 128 blocks; each block within one batch
    k_loss<<<BB, 256>>>(out);
}

// round 4
// speedup vs baseline: 1.9120x; 1.3833x over previous
#include <cuda_runtime.h>

#define BB    4
#define NN    8192
#define ALPHA 5.0f
#define EPS   1e-12f

#define SPLIT  8                 // ref-dimension split
#define SLICE  (NN / SPLIT)      // 1024 refs per block
#define SLICEP (SLICE / 2)       // 512 ref pairs per block (16 KB smem)
#define QB     128               // threads per knn block
#define QPT    4                 // queries per thread
#define QBLK   (QB * QPT)        // 512 queries per block

typedef unsigned long long ull;

// Packed ref pairs: pkA[p] = {x0,x1,y0,y1}, pkB[p] = {z0,z1,w0,w1}
__device__ float4 g_pkA[BB * NN / 2];
__device__ float4 g_pkB[BB * NN / 2];
__device__ float4 g_q4 [BB * NN];          // per-point (x,y,z,||p||^2)
__device__ float  g_part[BB * SPLIT * NN]; // per-(batch,slice,query) partial min
__device__ float  g_dsum[BB * NN];
__device__ float  g_bsum[BB];

__device__ __forceinline__ ull f2u(float a, float b) {
    union { float f[2]; ull u; } t; t.f[0] = a; t.f[1] = b; return t.u;
}
__device__ __forceinline__ void u2f(ull v, float& a, float& b) {
    union { float f[2]; ull u; } t; t.u = v; a = t.f[0]; b = t.f[1];
}
__device__ __forceinline__ ull fma2(ull a, ull b, ull c) {
    ull d; asm("fma.rn.f32x2 %0, %1, %2, %3;" : "=l"(d) : "l"(a), "l"(b), "l"(c)); return d;
}

// Pack refs; zero accumulators/output.
__global__ void k_prep(const float* __restrict__ xyz, float* __restrict__ out) {
    int p = blockIdx.x * blockDim.x + threadIdx.x;     // pair index
    if (p < BB * NN / 2) {
        const float2* g = (const float2*)xyz;
        float2 f0 = g[3*p+0], f1 = g[3*p+1], f2 = g[3*p+2];
        float x0 = f0.x, y0 = f0.y, z0 = f1.x;
        float x1 = f1.y, y1 = f2.x, z1 = f2.y;
        float w0 = (x0*x0 + y0*y0) + z0*z0;
        float w1 = (x1*x1 + y1*y1) + z1*z1;
        g_pkA[p] = make_float4(x0, x1, y0, y1);
        g_pkB[p] = make_float4(z0, z1, w0, w1);
        g_q4[2*p]   = make_float4(x0, y0, z0, w0);
        g_q4[2*p+1] = make_float4(x1, y1, z1, w1);
    }
    if (p == 0) {
        out[0] = 0.0f;
        #pragma unroll
        for (int b = 0; b < BB; b++) g_bsum[b] = 0.0f;
    }
}

// Each block: 512 queries (4/thread) vs a 1024-ref slice held in smem.
// Emits per-query partial m = min over slice of (w_j - 2*dot_j)
// (query's ||q||^2 added later; min commutes with the constant shift).
// The one block whose slice contains its own queries runs an exact 2-min
// and emits the second-smallest (self is the strict slice min there).
__global__ void __launch_bounds__(QB) k_knn() {
    __shared__ float4 sA[SLICEP];
    __shared__ float4 sB[SLICEP];

    const int b     = blockIdx.y;
    const int slice = blockIdx.z;
    const int tid   = threadIdx.x;
    const int qbase = blockIdx.x * QBLK + tid;

    const float4* __restrict__ pA = &g_pkA[b * (NN/2) + slice * SLICEP];
    const float4* __restrict__ pB = &g_pkB[b * (NN/2) + slice * SLICEP];
    #pragma unroll
    for (int j = tid; j < SLICEP; j += QB) {
        sA[j] = pA[j];
        sB[j] = pB[j];
    }

    ull mx[QPT], my[QPT], mz[QPT];
    #pragma unroll
    for (int k = 0; k < QPT; k++) {
        float4 q = g_q4[b * NN + qbase + k * QB];
        mx[k] = f2u(-2.0f*q.x, -2.0f*q.x);
        my[k] = f2u(-2.0f*q.y, -2.0f*q.y);
        mz[k] = f2u(-2.0f*q.z, -2.0f*q.z);
    }

    __syncthreads();

    const bool self_block = (slice == (blockIdx.x * QBLK) / SLICE);
    float part[QPT];

    if (!self_block) {
        // ---- fast path: plain min, 4 independent accumulators/query ----
        float a0[QPT], a1[QPT], a2[QPT], a3[QPT];
        #pragma unroll
        for (int k = 0; k < QPT; k++) { a0[k]=a1[k]=a2[k]=a3[k]=3.4e38f; }

        #pragma unroll 2
        for (int j = 0; j < SLICEP; j += 2) {
            float4 A0 = sA[j],   B0 = sB[j];
            float4 A1 = sA[j+1], B1 = sB[j+1];
            ull x0 = f2u(A0.x, A0.y), y0 = f2u(A0.z, A0.w);
            ull z0 = f2u(B0.x, B0.y), w0 = f2u(B0.z, B0.w);
            ull x1 = f2u(A1.x, A1.y), y1 = f2u(A1.z, A1.w);
            ull z1 = f2u(B1.x, B1.y), w1 = f2u(B1.z, B1.w);
            #pragma unroll
            for (int k = 0; k < QPT; k++) {
                ull t0 = fma2(mx[k], x0, fma2(my[k], y0, fma2(mz[k], z0, w0)));
                ull t1 = fma2(mx[k], x1, fma2(my[k], y1, fma2(mz[k], z1, w1)));
                float c0, c1, c2, c3;
                u2f(t0, c0, c1); u2f(t1, c2, c3);
                a0[k] = fminf(a0[k], c0);
                a1[k] = fminf(a1[k], c1);
                a2[k] = fminf(a2[k], c2);
                a3[k] = fminf(a3[k], c3);
            }
        }
        #pragma unroll
        for (int k = 0; k < QPT; k++)
            part[k] = fminf(fminf(a0[k], a1[k]), fminf(a2[k], a3[k]));
    } else {
        // ---- self path: exact 2-min; emit second smallest (min excl self) ----
        float s0[QPT], s1[QPT];
        #pragma unroll
        for (int k = 0; k < QPT; k++) { s0[k] = 3.4e38f; s1[k] = 3.4e38f; }

        for (int j = 0; j < SLICEP; j += 2) {
            float4 A0 = sA[j],   B0 = sB[j];
            float4 A1 = sA[j+1], B1 = sB[j+1];
            ull x0 = f2u(A0.x, A0.y), y0 = f2u(A0.z, A0.w);
            ull z0 = f2u(B0.x, B0.y), w0 = f2u(B0.z, B0.w);
            ull x1 = f2u(A1.x, A1.y), y1 = f2u(A1.z, A1.w);
            ull z1 = f2u(B1.x, B1.y), w1 = f2u(B1.z, B1.w);
            #pragma unroll
            for (int k = 0; k < QPT; k++) {
                ull t0 = fma2(mx[k], x0, fma2(my[k], y0, fma2(mz[k], z0, w0)));
                ull t1 = fma2(mx[k], x1, fma2(my[k], y1, fma2(mz[k], z1, w1)));
                float c0, c1, c2, c3;
                u2f(t0, c0, c1); u2f(t1, c2, c3);
                float m1 = fminf(c0, c1), M1 = fmaxf(c0, c1);
                float m2 = fminf(c2, c3), M2 = fmaxf(c2, c3);
                float v0 = fminf(m1, m2);
                float v1 = fminf(fmaxf(m1, m2), fminf(M1, M2));
                float n0 = fminf(v0, s0[k]);
                float tt = fmaxf(v0, s0[k]);
                float uu = fminf(v1, s1[k]);
                s0[k] = n0; s1[k] = fminf(tt, uu);
            }
        }
        #pragma unroll
        for (int k = 0; k < QPT; k++) part[k] = s1[k];
    }

    float* dst = &g_part[(b * SPLIT + slice) * NN];
    #pragma unroll
    for (int k = 0; k < QPT; k++) dst[qbase + k * QB] = part[k];
}

__device__ __forceinline__ float block_reduce_sum(float v) {
    __shared__ float sh[32];
    int lane = threadIdx.x & 31;
    int wid  = threadIdx.x >> 5;
    #pragma unroll
    for (int o = 16; o; o >>= 1) v += __shfl_down_sync(0xFFFFFFFFu, v, o);
    if (lane == 0) sh[wid] = v;
    __syncthreads();
    int nw = (blockDim.x + 31) >> 5;
    v = (threadIdx.x < nw) ? sh[threadIdx.x] : 0.0f;
    if (wid == 0) {
        #pragma unroll
        for (int o = 16; o; o >>= 1) v += __shfl_down_sync(0xFFFFFFFFu, v, o);
    }
    return v;
}

// One thread per query: merge SPLIT partial mins, add ||q||^2, compute
// self-distance directly, dsum = sqrt(self) + sqrt(nn); batch-sum via atomic.
__global__ void k_merge() {
    int i = blockIdx.x * blockDim.x + threadIdx.x;     // global query idx
    int b = i / NN;
    int q = i - b * NN;

    float m = g_part[(b * SPLIT + 0) * NN + q];
    #pragma unroll
    for (int s = 1; s < SPLIT; s++)
        m = fminf(m, g_part[(b * SPLIT + s) * NN + q]);

    float4 p = g_q4[i];
    float d2nn = p.w + m;   // ||q||^2 + min_j(w_j - 2 dot_j)
    // self d2 via the same fma-chain form
    float mself = fmaf(-2.0f*p.x, p.x, fmaf(-2.0f*p.y, p.y, fmaf(-2.0f*p.z, p.z, p.w)));
    float d2self = p.w + mself;

    float ds = sqrtf(fmaxf(d2self, EPS)) + sqrtf(fmaxf(d2nn, EPS));
    g_dsum[i] = ds;

    float t = block_reduce_sum(ds);                    // block within one batch
    if (threadIdx.x == 0) atomicAdd(&g_bsum[b], t);
}

// 128 blocks (32 per batch): masked sum where dsum > (bsum/N)*ALPHA
__global__ void k_loss(float* __restrict__ out) {
    int b = blockIdx.x >> 5;                 // 32 blocks per batch
    int chunk = blockIdx.x & 31;
    float avg = g_bsum[b] / (float)NN;       // mean, then *ALPHA (ref op order)
    float thr = avg * ALPHA;
    float d = g_dsum[b * NN + chunk * 256 + threadIdx.x];
    float s = (d > thr) ? d : 0.0f;
    s = block_reduce_sum(s);
    if (threadIdx.x == 0) atomicAdd(out, s);
}

extern "C" void kernel_launch(void* const* d_in, const int* in_sizes, int n_in,
                              void* d_out, int out_size) {
    const float* xyz = (const float*)d_in[0];
    float* out = (float*)d_out;

    k_prep<<<(BB * NN / 2 + 255) / 256, 256>>>(xyz, out);

    dim3 grid(NN / QBLK, BB, SPLIT);         // 16 x 4 x 8 = 512 blocks
    k_knn<<<grid, QB>>>();

    k_merge<<<BB * NN / 256, 256>>>();       // 128 blocks, batch-aligned
    k_loss<<<BB * 32, 256>>>(out);           // 128 blocks
}